// round 3
// baseline (speedup 1.0000x reference)
#include <cuda_runtime.h>
#include <cstdint>

// ---------------------------------------------------------------------------
// params computed on device by the prologue kernel
// g_params = { -p_off, -abar }  (negated so the log negation folds away)
// ---------------------------------------------------------------------------
__device__ float g_params[2];
__device__ uint32_t g_one;   // runtime 1, opaque to ptxas -> keeps IMADs on fma pipe

__global__ void abar_kernel(const float* __restrict__ beta,
                            const int* __restrict__ t_ptr) {
    int t = *t_ptr;
    int lane = threadIdx.x;  // 32 threads
    float prod = 1.0f;
    for (int i = lane; i < t; i += 32) prod *= (1.0f - beta[i]);
#pragma unroll
    for (int d = 16; d > 0; d >>= 1)
        prod *= __shfl_xor_sync(0xFFFFFFFFu, prod, d);
    if (lane == 0) {
        float abar = prod;
        float p_off = (1.0f - abar) * (1.0f / 256.0f);  // (1-abar)/K
        g_params[0] = -p_off;
        g_params[1] = -abar;          // -(p_diag - p_off)
        g_one = (t > -1000000) ? 1u : 2u;  // always 1, but runtime-dependent
    }
}

// ---------------------------------------------------------------------------
// integer adds routed to the FMA pipe: d = a*one + b  (one == 1 at runtime)
// ---------------------------------------------------------------------------
__device__ __forceinline__ uint32_t madd(uint32_t a, uint32_t b, uint32_t one) {
    uint32_t r;
    asm("mad.lo.u32 %0, %1, %2, %3;" : "=r"(r) : "r"(a), "r"(one), "r"(b));
    return r;
}
template <uint32_t IMM>
__device__ __forceinline__ uint32_t maddc(uint32_t x, uint32_t one) {
    uint32_t r;
    asm("mad.lo.u32 %0, %1, %2, %3;" : "=r"(r) : "r"(one), "n"(IMM), "r"(x));
    return r;  // x + IMM
}

__device__ __forceinline__ uint32_t rotl32(uint32_t x, int d) {
    return __funnelshift_l(x, x, d);
}

// threefry2x32, 20 rounds, key = (0,1). Partitionable layout:
// element i -> counter (0, i), output = o0 ^ o1.
__device__ __forceinline__ uint32_t threefry01_xor(uint32_t c1, uint32_t one) {
    const uint32_t ks2 = 0x1BD11BDBu;  // 0x1BD11BDA ^ 0 ^ 1
    // x0 = 0 + ks0 = 0 ; x1 = c1 + ks1 = c1 + 1
    uint32_t x1 = maddc<1u>(c1, one);
    // round 1 simplifies: x0 += x1 -> x0 = x1
    uint32_t x0 = x1;
    x1 = rotl32(x1, 13); x1 ^= x0;
#define TF_RND(R) { x0 = madd(x1, x0, one); x1 = rotl32(x1, R); x1 ^= x0; }
    TF_RND(15) TF_RND(26) TF_RND(6)
    x0 = maddc<1u>(x0, one);                 // += ks1
    x1 = maddc<0x1BD11BDCu>(x1, one);        // += ks2 + 1
    TF_RND(17) TF_RND(29) TF_RND(16) TF_RND(24)
    x0 = maddc<0x1BD11BDBu>(x0, one);        // += ks2
    x1 = maddc<2u>(x1, one);                 // += ks0 + 2
    TF_RND(13) TF_RND(15) TF_RND(26) TF_RND(6)
    /* x0 += ks0 (= 0): no-op */
    x1 = maddc<4u>(x1, one);                 // += ks1 + 3
    TF_RND(17) TF_RND(29) TF_RND(16) TF_RND(24)
    x0 = maddc<1u>(x0, one);                 // += ks1
    x1 = maddc<0x1BD11BDFu>(x1, one);        // += ks2 + 4
    TF_RND(13) TF_RND(15) TF_RND(26) TF_RND(6)
    x0 = maddc<0x1BD11BDBu>(x0, one);        // += ks2
    x1 = maddc<5u>(x1, one);                 // += ks0 + 5
#undef TF_RND
    return x0 ^ x1;
}

// jax uniform: f = bitcast((bits>>9)|0x3F800000) - 1 ; u = f + 1e-9
// (fmax(1e-9, .) is a no-op since f >= 0)
__device__ __forceinline__ float bits_to_u(uint32_t b) {
    float f = __uint_as_float((b >> 9) | 0x3F800000u) - 1.0f;
    return f + 1e-9f;
}

// ln(u) for u in [1e-9, 1): cephes-style, trimmed to 7 coefficients.
// Relative accuracy preserved as u -> 1 (x = m-1 exact); worst-case
// rel error ~1e-4 at the range-reduction edge -- well within 1e-3 budget.
__device__ __forceinline__ float log_fast(float u) {
    int ib = __float_as_int(u);
    int e = (ib >> 23) - 126;  // u = m * 2^e, m in [0.5, 1)
    float m = __int_as_float((ib & 0x007FFFFF) | 0x3F000000);
    if (m < 0.70710678f) { m = m + m; e -= 1; }
    float x = m - 1.0f;  // in [-0.2929, 0.4142], exact
    float z = x * x;
    float p =            1.1676998740e-1f;
    p = fmaf(p, x, -1.2420140846e-1f);
    p = fmaf(p, x,  1.4249322787e-1f);
    p = fmaf(p, x, -1.6668057665e-1f);
    p = fmaf(p, x,  2.0000714765e-1f);
    p = fmaf(p, x, -2.4999993993e-1f);
    p = fmaf(p, x,  3.3333331174e-1f);
    float y = p * (z * x);
    float fe = (float)e;
    y = fmaf(fe, -2.12194440e-4f, y);
    y = fmaf(-0.5f, z, y);
    float ln = x + y;
    return fmaf(fe, 0.693359375f, ln);   // negative for u < 1
}

// ---------------------------------------------------------------------------
// Main kernel: one warp per pixel. 256 channels -> 8 per lane (2x float4).
// ---------------------------------------------------------------------------
__global__ __launch_bounds__(256)
void gumbel_softmax_kernel(const float4* __restrict__ x0,
                           float4* __restrict__ out) {
    const int pixel = (blockIdx.x * blockDim.x + threadIdx.x) >> 5;  // [0,131072)
    const int lane = threadIdx.x & 31;

    const float n_off = g_params[0];   // -p_off
    const float n_dmo = g_params[1];   // -(p_diag - p_off) = -abar
    const uint32_t one = g_one;

    float w[8];
    float s = 0.0f;

#pragma unroll
    for (int half = 0; half < 2; half++) {
        const int vecIdx = lane + half * 32;          // float4 index in pixel
        float4 a = x0[pixel * 64 + vecIdx];
        float av[4] = {a.x, a.y, a.z, a.w};
        const uint32_t ibase = ((uint32_t)pixel << 8) + ((uint32_t)vecIdx << 2);
#pragma unroll
        for (int c = 0; c < 4; c++) {
            uint32_t bits = threefry01_xor(ibase + (uint32_t)c, one);
            float ln = log_fast(bits_to_u(bits));        // ln < 0
            float npv = fmaf(av[c], n_dmo, n_off);       // -(p_off + av*abar)
            float wv = __fdividef(npv, ln);              // (-p)/(ln) > 0
            w[half * 4 + c] = wv;
            s += wv;
        }
    }

#pragma unroll
    for (int d = 16; d > 0; d >>= 1)
        s += __shfl_xor_sync(0xFFFFFFFFu, s, d);
    const float inv = __fdividef(1.0f, s);

#pragma unroll
    for (int half = 0; half < 2; half++) {
        const int vecIdx = lane + half * 32;
        float4 o;
        o.x = w[half * 4 + 0] * inv;
        o.y = w[half * 4 + 1] * inv;
        o.z = w[half * 4 + 2] * inv;
        o.w = w[half * 4 + 3] * inv;
        out[pixel * 64 + vecIdx] = o;
    }
}

// ---------------------------------------------------------------------------
extern "C" void kernel_launch(void* const* d_in, const int* in_sizes, int n_in,
                              void* d_out, int out_size) {
    const float* x0   = (const float*)d_in[0];
    const float* beta = (const float*)d_in[1];
    const int*   t    = (const int*)d_in[2];
    float* out = (float*)d_out;

    abar_kernel<<<1, 32>>>(beta, t);
    // 131072 pixels -> 131072 warps -> 16384 blocks of 256 threads
    gumbel_softmax_kernel<<<16384, 256>>>((const float4*)x0, (float4*)out);
}

// round 4
// speedup vs baseline: 1.2615x; 1.2615x over previous
#include <cuda_runtime.h>
#include <cstdint>

// ---------------------------------------------------------------------------
// params: g_params = { a_off, a_dmo } with
//   a_off = -p_off/ln2 , a_dmo = -abar/ln2
// so that w = p/(-ln u) = fma(av, a_dmo, a_off) / log2(u)   (both negative)
// ---------------------------------------------------------------------------
__device__ float g_params[2];

__global__ void abar_kernel(const float* __restrict__ beta,
                            const int* __restrict__ t_ptr) {
    int t = *t_ptr;
    int lane = threadIdx.x;  // 32 threads
    float prod = 1.0f;
    for (int i = lane; i < t; i += 32) prod *= (1.0f - beta[i]);
#pragma unroll
    for (int d = 16; d > 0; d >>= 1)
        prod *= __shfl_xor_sync(0xFFFFFFFFu, prod, d);
    if (lane == 0) {
        float abar = prod;
        float p_off = (1.0f - abar) * (1.0f / 256.0f);   // (1-abar)/K
        const float inv_ln2 = 1.4426950408889634f;
        g_params[0] = -p_off * inv_ln2;
        g_params[1] = -abar * inv_ln2;    // -(p_diag - p_off)/ln2
    }
}

// ---------------------------------------------------------------------------
// threefry2x32, 20 rounds, key = (0,1)  (jax.random.key(1)).
// Partitionable layout: element i -> counter (0, i), output = o0 ^ o1.
// ---------------------------------------------------------------------------
__device__ __forceinline__ uint32_t rotl32(uint32_t x, int d) {
    return __funnelshift_l(x, x, d);
}

__device__ __forceinline__ uint32_t threefry01_xor(uint32_t c1) {
    const uint32_t ks2 = 0x1BD11BDBu;  // 0x1BD11BDA ^ 0 ^ 1
    // x0 = 0 + ks0 = 0 ; x1 = c1 + ks1 = c1 + 1
    uint32_t x1 = c1 + 1u;
    // round 1 simplifies: x0 += x1 -> x0 = x1
    uint32_t x0 = x1;
    x1 = rotl32(x1, 13); x1 ^= x0;
#define TF_RND(R) { x0 += x1; x1 = rotl32(x1, R); x1 ^= x0; }
    TF_RND(15) TF_RND(26) TF_RND(6)
    x0 += 1u;                 // += ks1
    x1 += ks2 + 1u;           // += ks2 + 1
    TF_RND(17) TF_RND(29) TF_RND(16) TF_RND(24)
    x0 += ks2;                // += ks2
    x1 += 2u;                 // += ks0 + 2
    TF_RND(13) TF_RND(15) TF_RND(26) TF_RND(6)
    /* x0 += ks0 (= 0): no-op */
    x1 += 4u;                 // += ks1 + 3
    TF_RND(17) TF_RND(29) TF_RND(16) TF_RND(24)
    x0 += 1u;                 // += ks1
    x1 += ks2 + 4u;           // += ks2 + 4
    TF_RND(13) TF_RND(15) TF_RND(26) TF_RND(6)
    x0 += ks2;                // += ks2
    x1 += 5u;                 // += ks0 + 5
#undef TF_RND
    return x0 ^ x1;
}

// jax uniform, bit-exact: u = rn( (bits>>9) * 2^-23 + 1e-9 )
// ((float)(bits>>9) is exact; single rounding matches bitcast-then-add path;
// fmax(1e-9,.) is a no-op since the value is >= 1e-9 already)
__device__ __forceinline__ float bits_to_u(uint32_t b) {
    return fmaf(__uint2float_rn(b >> 9), 0x1p-23f, 1e-9f);
}

// ---------------------------------------------------------------------------
// Main kernel: one warp per pixel. 256 channels -> 8 per lane (2x float4).
// w = p/(-ln u) computed as  fma(av, a_dmo, a_off) / log2f(u)
// (MUFU.LG2 + MUFU.RCP; log error self-cancels under softmax normalization)
// ---------------------------------------------------------------------------
__global__ __launch_bounds__(256)
void gumbel_softmax_kernel(const float4* __restrict__ x0,
                           float4* __restrict__ out) {
    const int pixel = (blockIdx.x * blockDim.x + threadIdx.x) >> 5;  // [0,131072)
    const int lane = threadIdx.x & 31;

    const float a_off = g_params[0];   // -p_off/ln2
    const float a_dmo = g_params[1];   // -abar/ln2

    float w[8];
    float s = 0.0f;

#pragma unroll
    for (int half = 0; half < 2; half++) {
        const int vecIdx = lane + half * 32;          // float4 index in pixel
        float4 a = x0[pixel * 64 + vecIdx];
        float av[4] = {a.x, a.y, a.z, a.w};
        const uint32_t ibase = ((uint32_t)pixel << 8) + ((uint32_t)vecIdx << 2);
#pragma unroll
        for (int c = 0; c < 4; c++) {
            uint32_t bits = threefry01_xor(ibase + (uint32_t)c);
            float lg = __log2f(bits_to_u(bits));          // < 0
            float npv = fmaf(av[c], a_dmo, a_off);        // < 0
            float wv = __fdividef(npv, lg);               // > 0
            w[half * 4 + c] = wv;
            s += wv;
        }
    }

#pragma unroll
    for (int d = 16; d > 0; d >>= 1)
        s += __shfl_xor_sync(0xFFFFFFFFu, s, d);
    const float inv = __fdividef(1.0f, s);

#pragma unroll
    for (int half = 0; half < 2; half++) {
        const int vecIdx = lane + half * 32;
        float4 o;
        o.x = w[half * 4 + 0] * inv;
        o.y = w[half * 4 + 1] * inv;
        o.z = w[half * 4 + 2] * inv;
        o.w = w[half * 4 + 3] * inv;
        out[pixel * 64 + vecIdx] = o;
    }
}

// ---------------------------------------------------------------------------
extern "C" void kernel_launch(void* const* d_in, const int* in_sizes, int n_in,
                              void* d_out, int out_size) {
    const float* x0   = (const float*)d_in[0];
    const float* beta = (const float*)d_in[1];
    const int*   t    = (const int*)d_in[2];
    float* out = (float*)d_out;

    abar_kernel<<<1, 32>>>(beta, t);
    // 131072 pixels -> 131072 warps -> 16384 blocks of 256 threads
    gumbel_softmax_kernel<<<16384, 256>>>((const float4*)x0, (float4*)out);
}

// round 5
// speedup vs baseline: 1.2823x; 1.0165x over previous
#include <cuda_runtime.h>
#include <cstdint>

// ---------------------------------------------------------------------------
// params: g_params = { a_off, a_dmo } with
//   a_off = -p_off/ln2 , a_dmo = -abar/ln2
// so that w = p/(-ln u) = fma(av, a_dmo, a_off) / log2(u)   (both negative)
// ---------------------------------------------------------------------------
__device__ float g_params[2];

__global__ void abar_kernel(const float* __restrict__ beta,
                            const int* __restrict__ t_ptr) {
    int t = *t_ptr;
    int lane = threadIdx.x;  // 32 threads
    float prod = 1.0f;
    for (int i = lane; i < t; i += 32) prod *= (1.0f - beta[i]);
#pragma unroll
    for (int d = 16; d > 0; d >>= 1)
        prod *= __shfl_xor_sync(0xFFFFFFFFu, prod, d);
    if (lane == 0) {
        float abar = prod;
        float p_off = (1.0f - abar) * (1.0f / 256.0f);   // (1-abar)/K
        const float inv_ln2 = 1.4426950408889634f;
        g_params[0] = -p_off * inv_ln2;
        g_params[1] = -abar * inv_ln2;    // -(p_diag - p_off)/ln2
    }
}

// ---------------------------------------------------------------------------
// threefry2x32, 20 rounds, key = (0,1)  (jax.random.key(1)).
// Partitionable layout: element i -> counter (0, i), output = o0 ^ o1.
// Key injections fused into 3-input adds (IADD3) with the next round's add.
// ---------------------------------------------------------------------------
__device__ __forceinline__ uint32_t rotl32(uint32_t x, int d) {
    return __funnelshift_l(x, x, d);
}

__device__ __forceinline__ uint32_t threefry01_xor(uint32_t c1) {
    const uint32_t ks2 = 0x1BD11BDBu;  // 0x1BD11BDA ^ 0 ^ 1
    // x0 = 0 + ks0 = 0 ; x1 = c1 + ks1 = c1 + 1 ; round 1: x0 += x1 -> x0 = x1
    uint32_t x1 = c1 + 1u;
    uint32_t x0 = x1;
    x1 = rotl32(x1, 13); x1 ^= x0;
#define TF_RND(R) { x0 += x1; x1 = rotl32(x1, R); x1 ^= x0; }
    TF_RND(15) TF_RND(26) TF_RND(6)
    // inj (ks1, ks2+1) fused with round add:
    x1 += ks2 + 1u;
    x0 = x0 + x1 + 1u;                  // IADD3
    x1 = rotl32(x1, 17); x1 ^= x0;
    TF_RND(29) TF_RND(16) TF_RND(24)
    // inj (ks2, ks0+2) fused:
    x1 += 2u;
    x0 = x0 + x1 + ks2;                 // IADD3
    x1 = rotl32(x1, 13); x1 ^= x0;
    TF_RND(15) TF_RND(26) TF_RND(6)
    // inj (ks0=0, ks1+3) fused:
    x1 += 4u;
    x0 = x0 + x1;
    x1 = rotl32(x1, 17); x1 ^= x0;
    TF_RND(29) TF_RND(16) TF_RND(24)
    // inj (ks1, ks2+4) fused:
    x1 += ks2 + 4u;
    x0 = x0 + x1 + 1u;                  // IADD3
    x1 = rotl32(x1, 13); x1 ^= x0;
    TF_RND(15) TF_RND(26) TF_RND(6)
    // final inj (ks2, ks0+5):
    x0 += ks2;
    x1 += 5u;
#undef TF_RND
    return x0 ^ x1;
}

// jax uniform, bit-exact: u = rn( (bits>>9) * 2^-23 + 1e-9 )
__device__ __forceinline__ float bits_to_u(uint32_t b) {
    return fmaf(__uint2float_rn(b >> 9), 0x1p-23f, 1e-9f);
}

// ---------------------------------------------------------------------------
// Main kernel: one warp per pixel. 256 channels -> 8 per lane (2x float4).
// All 8 threefry chains computed first (ILP-8 for the scheduler), then the
// float epilogue. __launch_bounds__(256, 4) -> 64-reg budget so ptxas can
// actually interleave the chains.
// ---------------------------------------------------------------------------
__global__ __launch_bounds__(256, 4)
void gumbel_softmax_kernel(const float4* __restrict__ x0,
                           float4* __restrict__ out) {
    const int pixel = (blockIdx.x * blockDim.x + threadIdx.x) >> 5;  // [0,131072)
    const int lane = threadIdx.x & 31;

    const float a_off = g_params[0];   // -p_off/ln2
    const float a_dmo = g_params[1];   // -abar/ln2

    // loads first
    const float4 a0 = x0[pixel * 64 + lane];
    const float4 a1 = x0[pixel * 64 + lane + 32];

    // 8 independent threefry chains
    const uint32_t base = ((uint32_t)pixel << 8) + ((uint32_t)lane << 2);
    uint32_t bits[8];
#pragma unroll
    for (int n = 0; n < 8; n++) {
        const uint32_t ctr = base + (uint32_t)((n >> 2) * 128 + (n & 3));
        bits[n] = threefry01_xor(ctr);
    }

    // float epilogue
    const float av[8] = {a0.x, a0.y, a0.z, a0.w, a1.x, a1.y, a1.z, a1.w};
    float w[8];
    float s = 0.0f;
#pragma unroll
    for (int n = 0; n < 8; n++) {
        float lg = __log2f(bits_to_u(bits[n]));        // < 0
        float npv = fmaf(av[n], a_dmo, a_off);         // < 0
        float wv = __fdividef(npv, lg);                // > 0
        w[n] = wv;
        s += wv;
    }

#pragma unroll
    for (int d = 16; d > 0; d >>= 1)
        s += __shfl_xor_sync(0xFFFFFFFFu, s, d);
    const float inv = __fdividef(1.0f, s);

    float4 o0, o1;
    o0.x = w[0] * inv; o0.y = w[1] * inv; o0.z = w[2] * inv; o0.w = w[3] * inv;
    o1.x = w[4] * inv; o1.y = w[5] * inv; o1.z = w[6] * inv; o1.w = w[7] * inv;
    out[pixel * 64 + lane]      = o0;
    out[pixel * 64 + lane + 32] = o1;
}

// ---------------------------------------------------------------------------
extern "C" void kernel_launch(void* const* d_in, const int* in_sizes, int n_in,
                              void* d_out, int out_size) {
    const float* x0   = (const float*)d_in[0];
    const float* beta = (const float*)d_in[1];
    const int*   t    = (const int*)d_in[2];
    float* out = (float*)d_out;

    abar_kernel<<<1, 32>>>(beta, t);
    // 131072 pixels -> 131072 warps -> 16384 blocks of 256 threads
    gumbel_softmax_kernel<<<16384, 256>>>((const float4*)x0, (float4*)out);
}